// round 1
// baseline (speedup 1.0000x reference)
#include <cuda_runtime.h>
#include <math.h>

#define EPSV 1e-5f
#define RS 144   // padded row stride for relative table in smem (bank-conflict-free phase C)

// 64 MiB scratch: qkv in layout [n][o][h][w], o in [0,256)
static __device__ float g_qkv[16 * 256 * 64 * 64];

// ---------------------------------------------------------------------------
// Kernel 1: qkv[n,o,h,w] = BN_qkv( sum_c w_qkv[o,c] * x[n,c,h,w] )
// Grid: (hw-tiles=64, o-tiles=4, n=16), 256 threads, 64x64 tile, 4x4 microtile
// ---------------------------------------------------------------------------
__global__ __launch_bounds__(256) void qkv_kernel(
    const float* __restrict__ x, const float* __restrict__ w,
    const float* __restrict__ bnq)
{
    __shared__ float ws[64][17];   // [o][c-chunk], padded
    __shared__ float xs[16][64];   // [c-chunk][hw]

    const int n   = blockIdx.z;
    const int o0  = blockIdx.y * 64;
    const int hw0 = blockIdx.x * 64;
    const int tid = threadIdx.x;
    const int tx  = tid & 15, ty = tid >> 4;

    float acc[4][4];
#pragma unroll
    for (int a = 0; a < 4; a++)
#pragma unroll
        for (int b = 0; b < 4; b++) acc[a][b] = 0.f;

    const float* xb = x + (size_t)n * 128 * 4096;

    for (int c0 = 0; c0 < 128; c0 += 16) {
        {   // load W tile (64 o x 16 c)
            int oo = tid >> 2, q = tid & 3;
            float4 wv = *(const float4*)&w[(o0 + oo) * 128 + c0 + q * 4];
            ws[oo][q * 4 + 0] = wv.x; ws[oo][q * 4 + 1] = wv.y;
            ws[oo][q * 4 + 2] = wv.z; ws[oo][q * 4 + 3] = wv.w;
        }
        {   // load x tile (16 c x 64 hw)
            int cc = tid >> 4, q = tid & 15;
            *(float4*)&xs[cc][q * 4] =
                *(const float4*)&xb[(size_t)(c0 + cc) * 4096 + hw0 + q * 4];
        }
        __syncthreads();
#pragma unroll
        for (int kk = 0; kk < 16; kk++) {
            float4 b4 = *(const float4*)&xs[kk][tx * 4];
            float bb0 = b4.x, bb1 = b4.y, bb2 = b4.z, bb3 = b4.w;
#pragma unroll
            for (int a = 0; a < 4; a++) {
                float av = ws[ty * 4 + a][kk];
                acc[a][0] += av * bb0;
                acc[a][1] += av * bb1;
                acc[a][2] += av * bb2;
                acc[a][3] += av * bb3;
            }
        }
        __syncthreads();
    }

    float* ob = g_qkv + (size_t)n * 256 * 4096;
#pragma unroll
    for (int a = 0; a < 4; a++) {
        int o = o0 + ty * 4 + a;
        float as = bnq[o] * rsqrtf(bnq[768 + o] + EPSV);
        float bs = bnq[256 + o] - as * bnq[512 + o];
        float4 r;
        r.x = as * acc[a][0] + bs;
        r.y = as * acc[a][1] + bs;
        r.z = as * acc[a][2] + bs;
        r.w = as * acc[a][3] + bs;
        *(float4*)&ob[(size_t)o * 4096 + hw0 + tx * 4] = r;
    }
}

// ---------------------------------------------------------------------------
// Kernel 2: fused attention per (n, g, 4 consecutive w)
// Grid: (wblk=16, g=8, n=16), 256 threads
// ---------------------------------------------------------------------------
__global__ __launch_bounds__(256, 2) void attn_kernel(
    const float* __restrict__ relative,
    const float* __restrict__ bns,   // (4,24)
    const float* __restrict__ bno,   // (4,256)
    float* __restrict__ out)
{
    extern __shared__ float sm[];
    float* rel  = sm;                     // 32*RS  = 4608
    float* sq   = rel + 32 * RS;          // 4*32*64 = 8192  ([wi][cc*64+h])
    float* ss   = sq + 8192;              // 64*65  = 4160
    float* invr = ss + 64 * 65;           // 64
    float* obuf = invr + 64;              // 16*64*4 = 4096

    const int wblk = blockIdx.x;
    const int g    = blockIdx.y;
    const int n    = blockIdx.z;
    const int w0   = wblk * 4;
    const int tid  = threadIdx.x;

    // relative -> smem (32 rows x 127, padded stride RS)
    for (int idx = tid; idx < 32 * 127; idx += 256) {
        int c = idx / 127, d = idx - c * 127;
        rel[c * RS + d] = relative[idx];
    }
    // qkv tile for 4 b's: float4 over w
    const float* qb = g_qkv + ((size_t)n * 256 + g * 32) * 4096 + w0;
    for (int idx = tid; idx < 2048; idx += 256) {   // idx = cc*64 + h
        float4 v = *(const float4*)&qb[(size_t)idx * 64];
        sq[idx]        = v.x;
        sq[2048 + idx] = v.y;
        sq[4096 + idx] = v.z;
        sq[6144 + idx] = v.w;
    }

    // bn_sim affine constants (fused: S = a_qk*qk + a_qr*qr + a_kr*kr + bsum)
    float a_qk, a_qr, a_kr, bsum;
    {
        int c0 = g, c1 = 8 + g, c2 = 16 + g;
        a_qk = bns[c0] * rsqrtf(bns[72 + c0] + EPSV);
        a_qr = bns[c1] * rsqrtf(bns[72 + c1] + EPSV);
        a_kr = bns[c2] * rsqrtf(bns[72 + c2] + EPSV);
        bsum = (bns[24 + c0] - a_qk * bns[48 + c0])
             + (bns[24 + c1] - a_qr * bns[48 + c1])
             + (bns[24 + c2] - a_kr * bns[48 + c2]);
    }

    const int ty = tid >> 4, tx = tid & 15;
    const int i0 = ty * 4, j0 = tx * 4;   // phase B microtile
    const int cc = ty;                    // phase C: v-channel in [0,16)
    const int ig = tx;                    // phase C: interleaved i base

    // bn_out affine constants for this thread's output channels
    float a0, a1, b01;
    {
        int ch0 = 2 * (g * 16 + cc), ch1 = ch0 + 1;
        a0 = bno[ch0] * rsqrtf(bno[768 + ch0] + EPSV);
        a1 = bno[ch1] * rsqrtf(bno[768 + ch1] + EPSV);
        b01 = (bno[256 + ch0] - a0 * bno[512 + ch0])
            + (bno[256 + ch1] - a1 * bno[512 + ch1]);
    }
    __syncthreads();

    for (int wi = 0; wi < 4; wi++) {
        const float* q_ = sq + wi * 2048;

        // ---- Phase B: S[i,j] (4x4 microtile per thread) ----
        float acc[4][4];
#pragma unroll
        for (int a = 0; a < 4; a++)
#pragma unroll
            for (int b = 0; b < 4; b++) acc[a][b] = bsum;

        const int db  = i0 - j0 + 60;   // base for rel[c, i-j+63], in [0,120]
        const int db2 = 120 - db;       // base for rel[8+c, j-i+63]
#pragma unroll
        for (int c = 0; c < 8; c++) {
            float4 q4 = *(const float4*)&q_[c * 64 + i0];
            float4 k4 = *(const float4*)&q_[(8 + c) * 64 + j0];
            float qv[4] = {q4.x, q4.y, q4.z, q4.w};
            float kv[4] = {k4.x, k4.y, k4.z, k4.w};
            const float* rq = rel + c * RS + db;
            const float* rk = rel + (8 + c) * RS + db2;
            float rqv[7], rkv[7];
#pragma unroll
            for (int t = 0; t < 7; t++) { rqv[t] = rq[t]; rkv[t] = rk[t]; }
            float kb[4];
#pragma unroll
            for (int b = 0; b < 4; b++) kb[b] = a_kr * kv[b];
#pragma unroll
            for (int a = 0; a < 4; a++) {
                float qa  = a_qk * qv[a];
                float qbr = a_qr * qv[a];
#pragma unroll
                for (int b = 0; b < 4; b++) {
                    acc[a][b] += qa  * kv[b];
                    acc[a][b] += qbr * rqv[3 + a - b];
                    acc[a][b] += kb[b] * rkv[3 + b - a];
                }
            }
        }
#pragma unroll
        for (int a = 0; a < 4; a++)
#pragma unroll
            for (int b = 0; b < 4; b++)
                ss[(i0 + a) * 65 + j0 + b] = acc[a][b];
        __syncthreads();

        // ---- Softmax over j (4 threads per row, quad shuffles) ----
        {
            int r = tid >> 2, qd = tid & 3;
            float* row = ss + r * 65 + qd * 16;
            float m = row[0];
#pragma unroll
            for (int t = 1; t < 16; t++) m = fmaxf(m, row[t]);
            m = fmaxf(m, __shfl_xor_sync(0xffffffffu, m, 1));
            m = fmaxf(m, __shfl_xor_sync(0xffffffffu, m, 2));
            float s = 0.f;
#pragma unroll
            for (int t = 0; t < 16; t++) {
                float e = __expf(row[t] - m);
                row[t] = e; s += e;
            }
            s += __shfl_xor_sync(0xffffffffu, s, 1);
            s += __shfl_xor_sync(0xffffffffu, s, 2);
            if (qd == 0) invr[r] = 1.0f / s;
        }
        __syncthreads();

        // ---- Phase C: sv/sve, BN_out, pair-sum (i interleaved: conflict-free) ----
        {
            const float* vrow = q_ + (16 + cc) * 64;
            const float* rrow = rel + (16 + cc) * RS;
            float sv[4] = {0, 0, 0, 0}, se[4] = {0, 0, 0, 0};
#pragma unroll 4
            for (int j = 0; j < 64; j++) {
                float vj = vrow[j];
#pragma unroll
                for (int a = 0; a < 4; a++) {
                    int i = ig + 16 * a;
                    float pij = ss[i * 65 + j];
                    sv[a] += pij * vj;
                    se[a] += pij * rrow[i - j + 63];
                }
            }
#pragma unroll
            for (int a = 0; a < 4; a++) {
                int i = ig + 16 * a;
                obuf[(cc * 64 + i) * 4 + wi] =
                    invr[i] * (a0 * sv[a] + a1 * se[a]) + b01;
            }
        }
        __syncthreads();
    }

    // ---- Final coalesced write: out[n, g*16+c, i, w0..w0+3] ----
    float* ob = out + ((size_t)(n * 128 + g * 16)) * 4096 + w0;
    for (int idx = tid; idx < 1024; idx += 256) {   // idx = c*64 + i
        *(float4*)&ob[(size_t)idx * 64] = *(const float4*)&obuf[idx * 4];
    }
}

// ---------------------------------------------------------------------------
extern "C" void kernel_launch(void* const* d_in, const int* in_sizes, int n_in,
                              void* d_out, int out_size)
{
    const float* x    = (const float*)d_in[0];
    const float* w    = (const float*)d_in[1];
    const float* relv = (const float*)d_in[2];
    const float* bnq  = (const float*)d_in[3];
    const float* bns  = (const float*)d_in[4];
    const float* bno  = (const float*)d_in[5];
    float* out = (float*)d_out;

    cudaFuncSetAttribute(attn_kernel,
                         cudaFuncAttributeMaxDynamicSharedMemorySize, 84480);

    qkv_kernel<<<dim3(64, 4, 16), 256>>>(x, w, bnq);
    attn_kernel<<<dim3(16, 8, 16), 256, 84480>>>(relv, bns, bno, out);
}

// round 3
// speedup vs baseline: 1.0606x; 1.0606x over previous
#include <cuda_runtime.h>
#include <math.h>

#define EPSV 1e-5f
#define RS 144   // padded row stride for relative table in smem (16B-aligned rows)

// 64 MiB scratch: qkv in layout [n][o][h][w], o in [0,256)
static __device__ float g_qkv[16 * 256 * 64 * 64];

// ---------------- f32x2 packed-FMA helpers (Blackwell FFMA2) ----------------
__device__ __forceinline__ unsigned long long pk2(float x, float y) {
    unsigned long long r;
    asm("mov.b64 %0, {%1, %2};" : "=l"(r) : "f"(x), "f"(y));
    return r;
}
__device__ __forceinline__ void fma2(unsigned long long& d,
                                     unsigned long long a, unsigned long long b) {
    asm("fma.rn.f32x2 %0, %1, %2, %0;" : "+l"(d) : "l"(a), "l"(b));
}
__device__ __forceinline__ float2 upk2(unsigned long long v) {
    float2 r;
    asm("mov.b64 {%0, %1}, %2;" : "=f"(r.x), "=f"(r.y) : "l"(v));
    return r;
}

// ---------------------------------------------------------------------------
// Kernel 1: qkv[n,o,h,w] = BN_qkv( sum_c w_qkv[o,c] * x[n,c,h,w] )
// Grid: (hw-tiles=32, o-tiles=4, n=16), 256 threads, 64x128 tile, 4x8 microtile
// Inner product in packed f32x2 (2 FLOP per FMA-pipe slot).
// ---------------------------------------------------------------------------
__global__ __launch_bounds__(256) void qkv_kernel(
    const float* __restrict__ x, const float* __restrict__ w,
    const float* __restrict__ bnq)
{
    __shared__ float wsT[16][68];   // [c-chunk][o], padded (transposed W)
    __shared__ float xs[16][128];   // [c-chunk][hw]

    const int n   = blockIdx.z;
    const int o0  = blockIdx.y * 64;
    const int hw0 = blockIdx.x * 128;
    const int tid = threadIdx.x;
    const int tx  = tid & 15, ty = tid >> 4;

    unsigned long long acc[4][4];   // [a][b-pair]; pair = 2 consecutive hw
#pragma unroll
    for (int a = 0; a < 4; a++)
#pragma unroll
        for (int p = 0; p < 4; p++) acc[a][p] = 0ull;

    const float* xb = x + (size_t)n * 128 * 4096;
    const int oo = tid >> 2, q = tid & 3;       // W loader mapping
    const int col = tx * 4;

    for (int c0 = 0; c0 < 128; c0 += 16) {
        {   // load W tile (64 o x 16 c), transposed into wsT[c][o]
            float4 wv = *(const float4*)&w[(o0 + oo) * 128 + c0 + q * 4];
            wsT[q * 4 + 0][oo] = wv.x; wsT[q * 4 + 1][oo] = wv.y;
            wsT[q * 4 + 2][oo] = wv.z; wsT[q * 4 + 3][oo] = wv.w;
        }
        {   // load x tile (16 c x 128 hw), two float4 halves per thread
            const float* xr = &xb[(size_t)(c0 + ty) * 4096 + hw0];
            *(float4*)&xs[ty][col]      = *(const float4*)&xr[col];
            *(float4*)&xs[ty][col + 64] = *(const float4*)&xr[col + 64];
        }
        __syncthreads();
#pragma unroll
        for (int kk = 0; kk < 16; kk++) {
            float4 a4  = *(const float4*)&wsT[kk][ty * 4];
            float4 b4a = *(const float4*)&xs[kk][col];
            float4 b4b = *(const float4*)&xs[kk][64 + col];
            unsigned long long bp[4];
            bp[0] = pk2(b4a.x, b4a.y); bp[1] = pk2(b4a.z, b4a.w);
            bp[2] = pk2(b4b.x, b4b.y); bp[3] = pk2(b4b.z, b4b.w);
            float av[4] = {a4.x, a4.y, a4.z, a4.w};
#pragma unroll
            for (int a = 0; a < 4; a++) {
                unsigned long long a2 = pk2(av[a], av[a]);
                fma2(acc[a][0], a2, bp[0]);
                fma2(acc[a][1], a2, bp[1]);
                fma2(acc[a][2], a2, bp[2]);
                fma2(acc[a][3], a2, bp[3]);
            }
        }
        __syncthreads();
    }

    float* ob = g_qkv + (size_t)n * 256 * 4096;
#pragma unroll
    for (int a = 0; a < 4; a++) {
        int o = o0 + ty * 4 + a;
        float as = bnq[o] * rsqrtf(bnq[768 + o] + EPSV);
        float bs = bnq[256 + o] - as * bnq[512 + o];
        float2 u0 = upk2(acc[a][0]), u1 = upk2(acc[a][1]);
        float2 u2 = upk2(acc[a][2]), u3 = upk2(acc[a][3]);
        float4 r1, r2;
        r1.x = as * u0.x + bs; r1.y = as * u0.y + bs;
        r1.z = as * u1.x + bs; r1.w = as * u1.y + bs;
        r2.x = as * u2.x + bs; r2.y = as * u2.y + bs;
        r2.z = as * u3.x + bs; r2.w = as * u3.y + bs;
        float* orow = &ob[(size_t)o * 4096 + hw0];
        *(float4*)&orow[col]      = r1;
        *(float4*)&orow[64 + col] = r2;
    }
}

// ---------------------------------------------------------------------------
// Kernel 2: fused attention per (n, g, 4 consecutive w)
// Grid: (wblk=16, g=8, n=16), 256 threads
// ---------------------------------------------------------------------------
__global__ __launch_bounds__(256, 2) void attn_kernel(
    const float* __restrict__ relative,
    const float* __restrict__ bns,   // (4,24)
    const float* __restrict__ bno,   // (4,256)
    float* __restrict__ out)
{
    extern __shared__ float sm[];
    float* rel  = sm;                     // 32*RS  = 4608
    float* sq   = rel + 32 * RS;          // 4*32*64 = 8192  ([wi][cc*64+h])
    float* ss   = sq + 8192;              // 64*65  = 4160
    float* invr = ss + 64 * 65;           // 64
    float* obuf = invr + 64;              // 16*64*4 = 4096

    const int wblk = blockIdx.x;
    const int g    = blockIdx.y;
    const int n    = blockIdx.z;
    const int w0   = wblk * 4;
    const int tid  = threadIdx.x;

    // relative -> smem (32 rows x 127, padded stride RS)
    for (int idx = tid; idx < 32 * 127; idx += 256) {
        int c = idx / 127, d = idx - c * 127;
        rel[c * RS + d] = relative[idx];
    }
    // qkv tile for 4 b's: float4 over w
    const float* qb = g_qkv + ((size_t)n * 256 + g * 32) * 4096 + w0;
    for (int idx = tid; idx < 2048; idx += 256) {   // idx = cc*64 + h
        float4 v = *(const float4*)&qb[(size_t)idx * 64];
        sq[idx]        = v.x;
        sq[2048 + idx] = v.y;
        sq[4096 + idx] = v.z;
        sq[6144 + idx] = v.w;
    }

    // bn_sim affine constants (fused: S = a_qk*qk + a_qr*qr + a_kr*kr + bsum)
    float a_qk, a_qr, a_kr, bsum;
    {
        int c0 = g, c1 = 8 + g, c2 = 16 + g;
        a_qk = bns[c0] * rsqrtf(bns[72 + c0] + EPSV);
        a_qr = bns[c1] * rsqrtf(bns[72 + c1] + EPSV);
        a_kr = bns[c2] * rsqrtf(bns[72 + c2] + EPSV);
        bsum = (bns[24 + c0] - a_qk * bns[48 + c0])
             + (bns[24 + c1] - a_qr * bns[48 + c1])
             + (bns[24 + c2] - a_kr * bns[48 + c2]);
    }

    const int ty = tid >> 4, tx = tid & 15;
    const int i0 = ty * 4, j0 = tx * 4;   // phase B microtile
    const int cc = ty;                    // phase C: v-channel in [0,16)
    const int ig = tx;                    // phase C: interleaved i base

    // bn_out affine constants for this thread's output channels
    float a0, a1, b01;
    {
        int ch0 = 2 * (g * 16 + cc), ch1 = ch0 + 1;
        a0 = bno[ch0] * rsqrtf(bno[768 + ch0] + EPSV);
        a1 = bno[ch1] * rsqrtf(bno[768 + ch1] + EPSV);
        b01 = (bno[256 + ch0] - a0 * bno[512 + ch0])
            + (bno[256 + ch1] - a1 * bno[512 + ch1]);
    }
    __syncthreads();

    for (int wi = 0; wi < 4; wi++) {
        const float* q_ = sq + wi * 2048;

        // ---- Phase B: S[i,j] (4x4 microtile per thread) ----
        float acc[4][4];
#pragma unroll
        for (int a = 0; a < 4; a++)
#pragma unroll
            for (int b = 0; b < 4; b++) acc[a][b] = bsum;

        const int db  = i0 - j0 + 60;   // mult of 4, in [0,120]
        const int db2 = 120 - db;       // mult of 4, in [0,120]
#pragma unroll
        for (int c = 0; c < 8; c++) {
            float4 q4 = *(const float4*)&q_[c * 64 + i0];
            float4 k4 = *(const float4*)&q_[(8 + c) * 64 + j0];
            float qv[4] = {q4.x, q4.y, q4.z, q4.w};
            float kv[4] = {k4.x, k4.y, k4.z, k4.w};
            // vectorized, conflict-free rel loads (16B-block consecutive lanes)
            const float* rq = rel + c * RS + db;
            const float* rk = rel + (8 + c) * RS + db2;
            float4 rqa = *(const float4*)rq;
            float4 rqb = *(const float4*)(rq + 4);
            float4 rka = *(const float4*)rk;
            float4 rkb = *(const float4*)(rk + 4);
            float rqv[8] = {rqa.x, rqa.y, rqa.z, rqa.w, rqb.x, rqb.y, rqb.z, rqb.w};
            float rkv[8] = {rka.x, rka.y, rka.z, rka.w, rkb.x, rkb.y, rkb.z, rkb.w};
            float kb[4];
#pragma unroll
            for (int b = 0; b < 4; b++) kb[b] = a_kr * kv[b];
#pragma unroll
            for (int a = 0; a < 4; a++) {
                float qa  = a_qk * qv[a];
                float qbr = a_qr * qv[a];
#pragma unroll
                for (int b = 0; b < 4; b++) {
                    acc[a][b] += qa  * kv[b];
                    acc[a][b] += qbr * rqv[3 + a - b];
                    acc[a][b] += kb[b] * rkv[3 + b - a];
                }
            }
        }
#pragma unroll
        for (int a = 0; a < 4; a++)
#pragma unroll
            for (int b = 0; b < 4; b++)
                ss[(i0 + a) * 65 + j0 + b] = acc[a][b];
        __syncthreads();

        // ---- Softmax over j (4 threads per row, quad shuffles) ----
        {
            int r = tid >> 2, qd = tid & 3;
            float* row = ss + r * 65 + qd * 16;
            float m = row[0];
#pragma unroll
            for (int t = 1; t < 16; t++) m = fmaxf(m, row[t]);
            m = fmaxf(m, __shfl_xor_sync(0xffffffffu, m, 1));
            m = fmaxf(m, __shfl_xor_sync(0xffffffffu, m, 2));
            float s = 0.f;
#pragma unroll
            for (int t = 0; t < 16; t++) {
                float e = __expf(row[t] - m);
                row[t] = e; s += e;
            }
            s += __shfl_xor_sync(0xffffffffu, s, 1);
            s += __shfl_xor_sync(0xffffffffu, s, 2);
            if (qd == 0) invr[r] = 1.0f / s;
        }
        __syncthreads();

        // ---- Phase C: sv/sve, BN_out, pair-sum (i interleaved: conflict-free) ----
        {
            const float* vrow = q_ + (16 + cc) * 64;
            const float* rrow = rel + (16 + cc) * RS;
            float sv[4] = {0, 0, 0, 0}, se[4] = {0, 0, 0, 0};
#pragma unroll 4
            for (int j4 = 0; j4 < 16; j4++) {
                float4 v4 = *(const float4*)&vrow[j4 * 4];
#pragma unroll
                for (int a = 0; a < 4; a++) {
                    int i = ig + 16 * a;
                    const float* prow = ss + i * 65 + j4 * 4;
                    const float* rb   = rrow + (i - j4 * 4 + 63);
                    float p0 = prow[0], p1 = prow[1], p2 = prow[2], p3 = prow[3];
                    sv[a] += p0 * v4.x + p1 * v4.y + p2 * v4.z + p3 * v4.w;
                    se[a] += p0 * rb[0] + p1 * rb[-1] + p2 * rb[-2] + p3 * rb[-3];
                }
            }
#pragma unroll
            for (int a = 0; a < 4; a++) {
                int i = ig + 16 * a;
                obuf[(cc * 64 + i) * 4 + wi] =
                    invr[i] * (a0 * sv[a] + a1 * se[a]) + b01;
            }
        }
        __syncthreads();
    }

    // ---- Final coalesced write: out[n, g*16+c, i, w0..w0+3] ----
    float* ob = out + ((size_t)(n * 128 + g * 16)) * 4096 + w0;
    for (int idx = tid; idx < 1024; idx += 256) {   // idx = c*64 + i
        *(float4*)&ob[(size_t)idx * 64] = *(const float4*)&obuf[idx * 4];
    }
}

// ---------------------------------------------------------------------------
extern "C" void kernel_launch(void* const* d_in, const int* in_sizes, int n_in,
                              void* d_out, int out_size)
{
    const float* x    = (const float*)d_in[0];
    const float* w    = (const float*)d_in[1];
    const float* relv = (const float*)d_in[2];
    const float* bnq  = (const float*)d_in[3];
    const float* bns  = (const float*)d_in[4];
    const float* bno  = (const float*)d_in[5];
    float* out = (float*)d_out;

    cudaFuncSetAttribute(attn_kernel,
                         cudaFuncAttributeMaxDynamicSharedMemorySize, 84480);

    qkv_kernel<<<dim3(32, 4, 16), 256>>>(x, w, bnq);
    attn_kernel<<<dim3(16, 8, 16), 256, 84480>>>(relv, bns, bno, out);
}